// round 1
// baseline (speedup 1.0000x reference)
#include <cuda_runtime.h>
#include <cuda_bf16.h>
#include <math.h>

// Problem dims (all compile-time)
static constexpr int Bsz = 16384;
static constexpr int Dd  = 768;
static constexpr int Kk  = 4;
static constexpr int H1  = 512;
static constexpr int H2  = 256;
static constexpr int KD  = Kk * Dd;   // 3072

// Scratch (device globals: allocation-free per harness rules)
__device__ float g_h1[Bsz * H1];        // 32 MB
__device__ float g_h2[Bsz * H2];        // 16 MB
__device__ float g_wflat[Bsz * KD];     // 201 MB
__device__ float g_logits[Bsz * Dd];    // 50 MB

// ---------------------------------------------------------------------------
// Classic register-blocked SGEMM: C[M,N] = A[M,K] @ B[K,N] + bias[N]
// BM=128 BN=128 BK=16, 256 threads, 8x8 per thread.
// Requires: M%128==0, N%128==0, K%16==0 (true for all 4 GEMMs here).
// ---------------------------------------------------------------------------
#define BM 128
#define BN 128
#define BKd 16
#define TM 8
#define TN 8

__global__ __launch_bounds__(256) void sgemm_bias(
    const float* __restrict__ A, const float* __restrict__ B,
    const float* __restrict__ bias, float* __restrict__ C,
    int M, int N, int Kdim)
{
    __shared__ float As[BKd][BM];
    __shared__ float Bs[BKd][BN];

    const int tid = threadIdx.x;
    const int bx = blockIdx.x;   // N tile
    const int by = blockIdx.y;   // M tile

    const float* Ab = A + (size_t)by * BM * Kdim;
    const float* Bb = B + (size_t)bx * BN;

    // global->shared load mapping
    const int aRow = tid >> 2;          // 0..63
    const int aCol = (tid & 3) << 2;    // 0,4,8,12
    const int bRow = tid >> 5;          // 0..7
    const int bCol = (tid & 31) << 2;   // 0..124

    // compute mapping: 16x16 thread grid, each 8x8
    const int tr = tid >> 4;
    const int tc = tid & 15;

    float acc[TM][TN];
    #pragma unroll
    for (int i = 0; i < TM; i++)
        #pragma unroll
        for (int j = 0; j < TN; j++) acc[i][j] = 0.f;

    for (int k0 = 0; k0 < Kdim; k0 += BKd) {
        // A tile (transposed into As[k][m])
        #pragma unroll
        for (int r = 0; r < 2; r++) {
            const int row = aRow + r * 64;
            float4 a = *(const float4*)(Ab + (size_t)row * Kdim + k0 + aCol);
            As[aCol + 0][row] = a.x;
            As[aCol + 1][row] = a.y;
            As[aCol + 2][row] = a.z;
            As[aCol + 3][row] = a.w;
        }
        // B tile
        #pragma unroll
        for (int r = 0; r < 2; r++) {
            const int row = bRow + r * 8;
            float4 b = *(const float4*)(Bb + (size_t)(k0 + row) * N + bCol);
            *(float4*)(&Bs[row][bCol]) = b;
        }
        __syncthreads();

        #pragma unroll
        for (int k = 0; k < BKd; k++) {
            float ra[TM], rb[TN];
            #pragma unroll
            for (int i = 0; i < TM; i += 4)
                *(float4*)(&ra[i]) = *(const float4*)(&As[k][tr * TM + i]);
            #pragma unroll
            for (int j = 0; j < TN; j += 4)
                *(float4*)(&rb[j]) = *(const float4*)(&Bs[k][tc * TN + j]);
            #pragma unroll
            for (int i = 0; i < TM; i++)
                #pragma unroll
                for (int j = 0; j < TN; j++)
                    acc[i][j] += ra[i] * rb[j];
        }
        __syncthreads();
    }

    // epilogue: + bias, vectorized store
    #pragma unroll
    for (int i = 0; i < TM; i++) {
        const int row = by * BM + tr * TM + i;
        #pragma unroll
        for (int j = 0; j < TN; j += 4) {
            const int col = bx * BN + tc * TN + j;
            float4 bv = *(const float4*)(bias + col);
            float4 v;
            v.x = acc[i][j + 0] + bv.x;
            v.y = acc[i][j + 1] + bv.y;
            v.z = acc[i][j + 2] + bv.z;
            v.w = acc[i][j + 3] + bv.w;
            *(float4*)(C + (size_t)row * N + col) = v;
        }
    }
}

// ---------------------------------------------------------------------------
// Block reductions (256 threads)
// ---------------------------------------------------------------------------
__device__ __forceinline__ float blockSum(float v, float* red) {
    #pragma unroll
    for (int o = 16; o > 0; o >>= 1) v += __shfl_down_sync(0xffffffffu, v, o);
    const int lane = threadIdx.x & 31, w = threadIdx.x >> 5;
    if (lane == 0) red[w] = v;
    __syncthreads();
    if (w == 0) {
        v = (lane < 8) ? red[lane] : 0.f;
        #pragma unroll
        for (int o = 4; o > 0; o >>= 1) v += __shfl_down_sync(0xffffffffu, v, o);
        if (lane == 0) red[0] = v;
    }
    __syncthreads();
    float out = red[0];
    __syncthreads();
    return out;
}

__device__ __forceinline__ float blockMax(float v, float* red) {
    #pragma unroll
    for (int o = 16; o > 0; o >>= 1) v = fmaxf(v, __shfl_down_sync(0xffffffffu, v, o));
    const int lane = threadIdx.x & 31, w = threadIdx.x >> 5;
    if (lane == 0) red[w] = v;
    __syncthreads();
    if (w == 0) {
        v = (lane < 8) ? red[lane] : -INFINITY;
        #pragma unroll
        for (int o = 4; o > 0; o >>= 1) v = fmaxf(v, __shfl_down_sync(0xffffffffu, v, o));
        if (lane == 0) red[0] = v;
    }
    __syncthreads();
    float out = red[0];
    __syncthreads();
    return out;
}

// ---------------------------------------------------------------------------
// LayerNorm + ReLU, in-place, one block per row (256 threads)
// ---------------------------------------------------------------------------
__global__ __launch_bounds__(256) void ln_relu(
    float* __restrict__ x, const float* __restrict__ g,
    const float* __restrict__ be, int H)
{
    __shared__ float red[32];
    float* xr = x + (size_t)blockIdx.x * H;
    const int tid = threadIdx.x;

    float s = 0.f, s2 = 0.f;
    for (int i = tid; i < H; i += 256) {
        float v = xr[i];
        s += v;
        s2 += v * v;
    }
    s  = blockSum(s, red);
    s2 = blockSum(s2, red);
    const float mu  = s / H;
    const float var = s2 / H - mu * mu;
    const float rs  = rsqrtf(var + 1e-5f);

    for (int i = tid; i < H; i += 256) {
        float v = (xr[i] - mu) * rs * g[i] + be[i];
        xr[i] = fmaxf(v, 0.f);
    }
}

// ---------------------------------------------------------------------------
// Fused epilogue: softmax(logits) -> attn; W = Wflat*attn; Gram-Schmidt K=4;
// writes W_ortho [B,K,D] and attn [B,D] into d_out.
// One block (256 threads) per row. Each thread owns D-indices
// {tid, tid+256, tid+512}: all vectors stay in registers.
// ---------------------------------------------------------------------------
__global__ __launch_bounds__(256) void epilogue_kernel(
    const float* __restrict__ wflat, const float* __restrict__ logits,
    float* __restrict__ out)
{
    __shared__ float red[32];
    const int row = blockIdx.x;
    const int tid = threadIdx.x;
    constexpr int J = Dd / 256;  // 3

    // ---- softmax over D=768 ----
    float l[J];
    float m = -INFINITY;
    #pragma unroll
    for (int j = 0; j < J; j++) {
        l[j] = logits[(size_t)row * Dd + tid + j * 256];
        m = fmaxf(m, l[j]);
    }
    m = blockMax(m, red);
    float e[J], s = 0.f;
    #pragma unroll
    for (int j = 0; j < J; j++) {
        e[j] = expf(l[j] - m);
        s += e[j];
    }
    s = blockSum(s, red);
    const float inv_s = 1.f / s;
    float attn[J];
    float* out_attn = out + (size_t)Bsz * KD;
    #pragma unroll
    for (int j = 0; j < J; j++) {
        attn[j] = e[j] * inv_s;
        out_attn[(size_t)row * Dd + tid + j * 256] = attn[j];
    }

    // ---- load W rows, modulate by attn ----
    float w[Kk][J];
    #pragma unroll
    for (int k = 0; k < Kk; k++)
        #pragma unroll
        for (int j = 0; j < J; j++)
            w[k][j] = wflat[(size_t)row * KD + k * Dd + tid + j * 256] * attn[j];

    // ---- Gram-Schmidt (matches reference order) ----
    #pragma unroll
    for (int k = 0; k < Kk; k++) {
        #pragma unroll
        for (int p = 0; p < k; p++) {
            float d = 0.f;
            #pragma unroll
            for (int j = 0; j < J; j++) d += w[k][j] * w[p][j];
            d = blockSum(d, red);
            #pragma unroll
            for (int j = 0; j < J; j++) w[k][j] -= d * w[p][j];
        }
        float n2 = 0.f;
        #pragma unroll
        for (int j = 0; j < J; j++) n2 += w[k][j] * w[k][j];
        n2 = blockSum(n2, red);
        const float inv = 1.f / fmaxf(sqrtf(n2), 1e-12f);
        #pragma unroll
        for (int j = 0; j < J; j++) {
            w[k][j] *= inv;
            out[(size_t)row * KD + k * Dd + tid + j * 256] = w[k][j];
        }
    }
}

// ---------------------------------------------------------------------------
extern "C" void kernel_launch(void* const* d_in, const int* in_sizes, int n_in,
                              void* d_out, int out_size)
{
    const float* emb = (const float*)d_in[0];
    const float* W1  = (const float*)d_in[1];
    const float* b1  = (const float*)d_in[2];
    const float* g1  = (const float*)d_in[3];
    const float* be1 = (const float*)d_in[4];
    const float* W2  = (const float*)d_in[5];
    const float* b2  = (const float*)d_in[6];
    const float* g2  = (const float*)d_in[7];
    const float* be2 = (const float*)d_in[8];
    const float* Wd  = (const float*)d_in[9];
    const float* bd  = (const float*)d_in[10];
    const float* Wa  = (const float*)d_in[11];
    const float* ba  = (const float*)d_in[12];
    float* out = (float*)d_out;

    float *h1, *h2, *wflat, *logits;
    cudaGetSymbolAddress((void**)&h1, g_h1);
    cudaGetSymbolAddress((void**)&h2, g_h2);
    cudaGetSymbolAddress((void**)&wflat, g_wflat);
    cudaGetSymbolAddress((void**)&logits, g_logits);

    // Layer 1: emb[B,768] @ W1[768,512] + b1 -> LN -> relu
    sgemm_bias<<<dim3(H1 / BN, Bsz / BM), 256>>>(emb, W1, b1, h1, Bsz, H1, Dd);
    ln_relu<<<Bsz, 256>>>(h1, g1, be1, H1);

    // Layer 2: h1[B,512] @ W2[512,256] + b2 -> LN -> relu
    sgemm_bias<<<dim3(H2 / BN, Bsz / BM), 256>>>(h1, W2, b2, h2, Bsz, H2, H1);
    ln_relu<<<Bsz, 256>>>(h2, g2, be2, H2);

    // Heads: Wflat = h2 @ Wd + bd ; logits = h2 @ Wa + ba
    sgemm_bias<<<dim3(KD / BN, Bsz / BM), 256>>>(h2, Wd, bd, wflat, Bsz, KD, H2);
    sgemm_bias<<<dim3(Dd / BN, Bsz / BM), 256>>>(h2, Wa, ba, logits, Bsz, Dd, H2);

    // softmax + modulate + Gram-Schmidt + writes
    epilogue_kernel<<<Bsz, 256>>>(wflat, logits, out);
}

// round 3
// speedup vs baseline: 1.8327x; 1.8327x over previous
#include <cuda_runtime.h>
#include <cuda_bf16.h>
#include <math.h>
#include <cstdint>

// Problem dims (compile-time)
static constexpr int Bsz = 16384;
static constexpr int Dd  = 768;
static constexpr int Kk  = 4;
static constexpr int H1  = 512;
static constexpr int H2  = 256;
static constexpr int KD  = Kk * Dd;   // 3072

// Scratch (device globals: allocation-free per harness rules)
__device__ float g_h1[Bsz * H1];
__device__ float g_h2[Bsz * H2];
__device__ float g_wflat[Bsz * KD];
__device__ float g_logits[Bsz * Dd];

// fp32 -> tf32 with round-to-nearest (better than HW truncation inside mma)
__device__ __forceinline__ uint32_t rn_tf32(float x) {
    uint32_t u;
    asm("cvt.rna.tf32.f32 %0, %1;" : "=r"(u) : "f"(x));
    return u;
}

// ===========================================================================
// TF32 mma.sync GEMM: C[M,N] = A[M,K] @ B[K,N] + bias[N]
// BM=128, BN=128, BK=32. 256 threads = 8 warps in 2x4 (m x n) grid.
// Warp tile 64x32 = 4x4 mma tiles of m16n8k8. fp32 accumulate.
// Requires M%128==0, N%128==0, K%32==0 (true for all 4 GEMMs).
// ===========================================================================
#define BM 128
#define BN 128
#define BKt 32

// smem pads chosen for conflict-free fragment LDS:
//  A stride 36: addr%32banks = (4*row + k)%32, distinct for row 0..7 x k 0..3
//  B stride 136: (8*k + n)%32, distinct for k 0..3 x n 0..7
__global__ __launch_bounds__(256, 2) void mma_gemm(
    const float* __restrict__ A, const float* __restrict__ B,
    const float* __restrict__ bias, float* __restrict__ C,
    int M, int N, int Kdim)
{
    __shared__ uint32_t As[BM][36];
    __shared__ uint32_t Bs[BKt][136];

    const int tid  = threadIdx.x;
    const int lane = tid & 31;
    const int w    = tid >> 5;
    const int wm   = w >> 2;          // 0..1
    const int wn   = w & 3;           // 0..3
    const int gid  = lane >> 2;       // 0..7
    const int tig  = lane & 3;        // 0..3

    const int m0 = blockIdx.y * BM;
    const int n0 = blockIdx.x * BN;

    // global->smem mapping
    const int aRow = tid >> 1;              // 0..127
    const int aK0  = (tid & 1) * 16;        // 0 or 16
    const int bRow = tid >> 3;              // 0..31
    const int bC0  = (tid & 7) * 16;        // 0..112

    float acc[4][4][4];
    #pragma unroll
    for (int i = 0; i < 4; i++)
        #pragma unroll
        for (int j = 0; j < 4; j++)
            #pragma unroll
            for (int r = 0; r < 4; r++) acc[i][j][r] = 0.f;

    for (int k0 = 0; k0 < Kdim; k0 += BKt) {
        // A tile: 128 x 32 floats
        {
            const float* Ap = A + (size_t)(m0 + aRow) * Kdim + k0 + aK0;
            #pragma unroll
            for (int jj = 0; jj < 4; jj++) {
                float4 v = *(const float4*)(Ap + jj * 4);
                uint4 u = make_uint4(rn_tf32(v.x), rn_tf32(v.y), rn_tf32(v.z), rn_tf32(v.w));
                *(uint4*)(&As[aRow][aK0 + jj * 4]) = u;
            }
        }
        // B tile: 32 x 128 floats
        {
            const float* Bp = B + (size_t)(k0 + bRow) * N + n0 + bC0;
            #pragma unroll
            for (int jj = 0; jj < 4; jj++) {
                float4 v = *(const float4*)(Bp + jj * 4);
                uint4 u = make_uint4(rn_tf32(v.x), rn_tf32(v.y), rn_tf32(v.z), rn_tf32(v.w));
                *(uint4*)(&Bs[bRow][bC0 + jj * 4]) = u;
            }
        }
        __syncthreads();

        #pragma unroll
        for (int ks = 0; ks < 4; ks++) {
            const int kb = ks * 8;
            // A fragments: 4 m-tiles x 4 regs
            uint32_t af[4][4];
            #pragma unroll
            for (int mi = 0; mi < 4; mi++) {
                const int r = wm * 64 + mi * 16 + gid;
                af[mi][0] = As[r    ][kb + tig    ];
                af[mi][1] = As[r + 8][kb + tig    ];
                af[mi][2] = As[r    ][kb + tig + 4];
                af[mi][3] = As[r + 8][kb + tig + 4];
            }
            // B fragments: 4 n-tiles x 2 regs
            uint32_t bf[4][2];
            #pragma unroll
            for (int ni = 0; ni < 4; ni++) {
                const int c = wn * 32 + ni * 8 + gid;
                bf[ni][0] = Bs[kb + tig    ][c];
                bf[ni][1] = Bs[kb + tig + 4][c];
            }
            #pragma unroll
            for (int mi = 0; mi < 4; mi++)
                #pragma unroll
                for (int ni = 0; ni < 4; ni++) {
                    asm volatile(
                        "mma.sync.aligned.m16n8k8.row.col.f32.tf32.tf32.f32 "
                        "{%0,%1,%2,%3}, {%4,%5,%6,%7}, {%8,%9}, {%0,%1,%2,%3};"
                        : "+f"(acc[mi][ni][0]), "+f"(acc[mi][ni][1]),
                          "+f"(acc[mi][ni][2]), "+f"(acc[mi][ni][3])
                        : "r"(af[mi][0]), "r"(af[mi][1]), "r"(af[mi][2]), "r"(af[mi][3]),
                          "r"(bf[ni][0]), "r"(bf[ni][1]));
                }
        }
        __syncthreads();
    }

    // Epilogue: + bias, float2 stores straight from fragments
    #pragma unroll
    for (int mi = 0; mi < 4; mi++) {
        const int r0 = m0 + wm * 64 + mi * 16 + gid;
        #pragma unroll
        for (int ni = 0; ni < 4; ni++) {
            const int c = n0 + wn * 32 + ni * 8 + tig * 2;
            const float2 bv = *(const float2*)(bias + c);
            float2 v0, v1;
            v0.x = acc[mi][ni][0] + bv.x;
            v0.y = acc[mi][ni][1] + bv.y;
            v1.x = acc[mi][ni][2] + bv.x;
            v1.y = acc[mi][ni][3] + bv.y;
            *(float2*)(C + (size_t)r0 * N + c)       = v0;
            *(float2*)(C + (size_t)(r0 + 8) * N + c) = v1;
        }
    }
}

// ===========================================================================
// Block reductions
// ===========================================================================
__device__ __forceinline__ float blockSumN(float v, float* red, int nw) {
    #pragma unroll
    for (int o = 16; o > 0; o >>= 1) v += __shfl_down_sync(0xffffffffu, v, o);
    const int lane = threadIdx.x & 31, w = threadIdx.x >> 5;
    if (lane == 0) red[w] = v;
    __syncthreads();
    if (w == 0) {
        v = (lane < nw) ? red[lane] : 0.f;
        #pragma unroll
        for (int o = 4; o > 0; o >>= 1) v += __shfl_down_sync(0xffffffffu, v, o);
        if (lane == 0) red[0] = v;
    }
    __syncthreads();
    float out = red[0];
    __syncthreads();
    return out;
}

__device__ __forceinline__ float blockMaxN(float v, float* red, int nw) {
    #pragma unroll
    for (int o = 16; o > 0; o >>= 1) v = fmaxf(v, __shfl_down_sync(0xffffffffu, v, o));
    const int lane = threadIdx.x & 31, w = threadIdx.x >> 5;
    if (lane == 0) red[w] = v;
    __syncthreads();
    if (w == 0) {
        v = (lane < nw) ? red[lane] : -INFINITY;
        #pragma unroll
        for (int o = 4; o > 0; o >>= 1) v = fmaxf(v, __shfl_down_sync(0xffffffffu, v, o));
        if (lane == 0) red[0] = v;
    }
    __syncthreads();
    float out = red[0];
    __syncthreads();
    return out;
}

// ===========================================================================
// One-pass LayerNorm + ReLU: block = H/4 threads, one float4 per thread
// ===========================================================================
__global__ void ln_relu_v2(float* __restrict__ x, const float* __restrict__ g,
                           const float* __restrict__ be)
{
    __shared__ float red[8];
    const int H = blockDim.x * 4;
    const int nw = blockDim.x >> 5;
    float4* xp = (float4*)(x + (size_t)blockIdx.x * H);
    float4 v = xp[threadIdx.x];

    float s  = v.x + v.y + v.z + v.w;
    float s2 = v.x * v.x + v.y * v.y + v.z * v.z + v.w * v.w;
    s  = blockSumN(s, red, nw);
    s2 = blockSumN(s2, red, nw);
    const float mu  = s / H;
    const float var = s2 / H - mu * mu;
    const float rs  = rsqrtf(var + 1e-5f);

    float4 gg = ((const float4*)g)[threadIdx.x];
    float4 bb = ((const float4*)be)[threadIdx.x];
    v.x = fmaxf((v.x - mu) * rs * gg.x + bb.x, 0.f);
    v.y = fmaxf((v.y - mu) * rs * gg.y + bb.y, 0.f);
    v.z = fmaxf((v.z - mu) * rs * gg.z + bb.z, 0.f);
    v.w = fmaxf((v.w - mu) * rs * gg.w + bb.w, 0.f);
    xp[threadIdx.x] = v;
}

// ===========================================================================
// Fused epilogue: softmax -> attn; W = Wflat*attn; Gram-Schmidt K=4; writes
// W_ortho [B,K,D] and attn [B,D]. One 256-thread block per row; vectors in regs.
// ===========================================================================
__global__ __launch_bounds__(256) void epilogue_kernel(
    const float* __restrict__ wflat, const float* __restrict__ logits,
    float* __restrict__ out)
{
    __shared__ float red[8];
    const int row = blockIdx.x;
    const int tid = threadIdx.x;
    constexpr int J = Dd / 256;  // 3

    float l[J];
    float m = -INFINITY;
    #pragma unroll
    for (int j = 0; j < J; j++) {
        l[j] = logits[(size_t)row * Dd + tid + j * 256];
        m = fmaxf(m, l[j]);
    }
    m = blockMaxN(m, red, 8);
    float e[J], s = 0.f;
    #pragma unroll
    for (int j = 0; j < J; j++) { e[j] = expf(l[j] - m); s += e[j]; }
    s = blockSumN(s, red, 8);
    const float inv_s = 1.f / s;
    float attn[J];
    float* out_attn = out + (size_t)Bsz * KD;
    #pragma unroll
    for (int j = 0; j < J; j++) {
        attn[j] = e[j] * inv_s;
        out_attn[(size_t)row * Dd + tid + j * 256] = attn[j];
    }

    float wv[Kk][J];
    #pragma unroll
    for (int k = 0; k < Kk; k++)
        #pragma unroll
        for (int j = 0; j < J; j++)
            wv[k][j] = wflat[(size_t)row * KD + k * Dd + tid + j * 256] * attn[j];

    #pragma unroll
    for (int k = 0; k < Kk; k++) {
        #pragma unroll
        for (int p = 0; p < k; p++) {
            float d = 0.f;
            #pragma unroll
            for (int j = 0; j < J; j++) d += wv[k][j] * wv[p][j];
            d = blockSumN(d, red, 8);
            #pragma unroll
            for (int j = 0; j < J; j++) wv[k][j] -= d * wv[p][j];
        }
        float n2 = 0.f;
        #pragma unroll
        for (int j = 0; j < J; j++) n2 += wv[k][j] * wv[k][j];
        n2 = blockSumN(n2, red, 8);
        const float inv = 1.f / fmaxf(sqrtf(n2), 1e-12f);
        #pragma unroll
        for (int j = 0; j < J; j++) {
            wv[k][j] *= inv;
            out[(size_t)row * KD + k * Dd + tid + j * 256] = wv[k][j];
        }
    }
}

// ===========================================================================
extern "C" void kernel_launch(void* const* d_in, const int* in_sizes, int n_in,
                              void* d_out, int out_size)
{
    const float* emb = (const float*)d_in[0];
    const float* W1  = (const float*)d_in[1];
    const float* b1  = (const float*)d_in[2];
    const float* g1  = (const float*)d_in[3];
    const float* be1 = (const float*)d_in[4];
    const float* W2  = (const float*)d_in[5];
    const float* b2  = (const float*)d_in[6];
    const float* g2  = (const float*)d_in[7];
    const float* be2 = (const float*)d_in[8];
    const float* Wd  = (const float*)d_in[9];
    const float* bd  = (const float*)d_in[10];
    const float* Wa  = (const float*)d_in[11];
    const float* ba  = (const float*)d_in[12];
    float* out = (float*)d_out;

    float *h1, *h2, *wflat, *logits;
    cudaGetSymbolAddress((void**)&h1, g_h1);
    cudaGetSymbolAddress((void**)&h2, g_h2);
    cudaGetSymbolAddress((void**)&wflat, g_wflat);
    cudaGetSymbolAddress((void**)&logits, g_logits);

    // Layer 1: emb[B,768] @ W1[768,512] + b1 -> LN -> relu
    mma_gemm<<<dim3(H1 / BN, Bsz / BM), 256>>>(emb, W1, b1, h1, Bsz, H1, Dd);
    ln_relu_v2<<<Bsz, H1 / 4>>>(h1, g1, be1);
    // Layer 2: h1[B,512] @ W2[512,256] + b2 -> LN -> relu
    mma_gemm<<<dim3(H2 / BN, Bsz / BM), 256>>>(h1, W2, b2, h2, Bsz, H2, H1);
    ln_relu_v2<<<Bsz, H2 / 4>>>(h2, g2, be2);
    // Heads
    mma_gemm<<<dim3(KD / BN, Bsz / BM), 256>>>(h2, Wd, bd, wflat, Bsz, KD, H2);
    mma_gemm<<<dim3(Dd / BN, Bsz / BM), 256>>>(h2, Wa, ba, logits, Bsz, Dd, H2);
    // softmax + modulate + Gram-Schmidt
    epilogue_kernel<<<Bsz, 256>>>(wflat, logits, out);
}

// round 5
// speedup vs baseline: 1.8329x; 1.0001x over previous
#include <cuda_runtime.h>
#include <cuda_bf16.h>
#include <math.h>
#include <cstdint>

// Problem dims (compile-time)
static constexpr int Bsz = 16384;
static constexpr int Dd  = 768;
static constexpr int Kk  = 4;
static constexpr int H1  = 512;
static constexpr int H2  = 256;
static constexpr int KD  = Kk * Dd;   // 3072

// Scratch (device globals: allocation-free per harness rules)
__device__ float g_h1[Bsz * H1];
__device__ float g_h2[Bsz * H2];
__device__ float g_wflat[Bsz * KD];
__device__ float g_logits[Bsz * Dd];

// fp32 -> tf32 with round-to-nearest (same numerics as R3)
__device__ __forceinline__ uint32_t rn_tf32(float x) {
    uint32_t u;
    asm("cvt.rna.tf32.f32 %0, %1;" : "=r"(u) : "f"(x));
    return u;
}

__device__ __forceinline__ uint32_t smem_u32(const void* p) {
    uint32_t a;
    asm("{ .reg .u64 t; cvta.to.shared.u64 t, %1; cvt.u32.u64 %0, t; }"
        : "=r"(a) : "l"(p));
    return a;
}

__device__ __forceinline__ void cp_async16(void* dst, const void* src) {
    asm volatile("cp.async.cg.shared.global [%0], [%1], 16;"
                 :: "r"(smem_u32(dst)), "l"(src) : "memory");
}
#define CP_COMMIT() asm volatile("cp.async.commit_group;" ::: "memory")
#define CP_WAIT(n)  asm volatile("cp.async.wait_group %0;" :: "n"(n) : "memory")

// ===========================================================================
// TF32 mma.sync GEMM, cp.async double-buffered, DYNAMIC smem (>48KB).
// C[M,N] = A[M,K] @ B[K,N] + bias[N]
// BM=128, BN=128, BK=32. 256 threads = 8 warps in 2x4 (m x n) grid.
// Warp tile 64x32 = 4x4 mma tiles of m16n8k8, fp32 accumulate.
// Requires M%128==0, N%128==0, K%32==0 (true for all 4 GEMMs).
// ===========================================================================
#define BM 128
#define BN 128
#define BKt 32

// smem pads for conflict-free fragment LDS:
//  A stride 36: (4*row + k)%32 distinct for row 0..7 x k 0..3
//  B stride 136: (8*k + n)%32 distinct for k 0..3 x n 0..7
static constexpr int AS_STRIDE = 36;
static constexpr int BS_STRIDE = 136;
static constexpr int AS_ELEMS  = BM * AS_STRIDE;    // 4608 floats / buffer
static constexpr int BS_ELEMS  = BKt * BS_STRIDE;   // 4352 floats / buffer
static constexpr int GEMM_SMEM_BYTES = (2 * AS_ELEMS + 2 * BS_ELEMS) * 4;  // 71680

__global__ __launch_bounds__(256, 2) void mma_gemm(
    const float* __restrict__ A, const float* __restrict__ B,
    const float* __restrict__ bias, float* __restrict__ C,
    int M, int N, int Kdim)
{
    extern __shared__ float smem[];
    // layout: As[0], As[1], Bs[0], Bs[1]
    float* AsBuf[2] = { smem, smem + AS_ELEMS };
    float* BsBuf[2] = { smem + 2 * AS_ELEMS, smem + 2 * AS_ELEMS + BS_ELEMS };
    #define ASM(b, r, c) AsBuf[b][(r) * AS_STRIDE + (c)]
    #define BSM(b, r, c) BsBuf[b][(r) * BS_STRIDE + (c)]

    const int tid  = threadIdx.x;
    const int lane = tid & 31;
    const int w    = tid >> 5;
    const int wm   = w >> 2;          // 0..1
    const int wn   = w & 3;           // 0..3
    const int gid  = lane >> 2;       // 0..7
    const int tig  = lane & 3;        // 0..3

    const int m0 = blockIdx.y * BM;
    const int n0 = blockIdx.x * BN;

    // global->smem mapping (16 floats per thread per tile, 4x 16B cp.async)
    const int aRow = tid >> 1;              // 0..127
    const int aK0  = (tid & 1) * 16;        // 0 or 16
    const int bRow = tid >> 3;              // 0..31
    const int bC0  = (tid & 7) * 16;        // 0..112

    const float* ApBase = A + (size_t)(m0 + aRow) * Kdim + aK0;
    const float* BpBase = B + (size_t)bRow * N + n0 + bC0;

    float acc[4][4][4];
    #pragma unroll
    for (int i = 0; i < 4; i++)
        #pragma unroll
        for (int j = 0; j < 4; j++)
            #pragma unroll
            for (int r = 0; r < 4; r++) acc[i][j][r] = 0.f;

    const int nch = Kdim / BKt;

    // prologue: stage chunk 0 into buffer 0
    {
        #pragma unroll
        for (int jj = 0; jj < 4; jj++)
            cp_async16(&ASM(0, aRow, aK0 + jj * 4), ApBase + jj * 4);
        #pragma unroll
        for (int jj = 0; jj < 4; jj++)
            cp_async16(&BSM(0, bRow, bC0 + jj * 4), BpBase + jj * 4);
        CP_COMMIT();
    }

    for (int kc = 0; kc < nch; kc++) {
        const int cur = kc & 1;
        // prefetch chunk kc+1 into the other buffer (safe: its readers
        // finished at the trailing __syncthreads of iter kc-1)
        if (kc + 1 < nch) {
            const int nxt = cur ^ 1;
            const float* Ap = ApBase + (kc + 1) * BKt;
            const float* Bp = BpBase + (size_t)(kc + 1) * BKt * N;
            #pragma unroll
            for (int jj = 0; jj < 4; jj++)
                cp_async16(&ASM(nxt, aRow, aK0 + jj * 4), Ap + jj * 4);
            #pragma unroll
            for (int jj = 0; jj < 4; jj++)
                cp_async16(&BSM(nxt, bRow, bC0 + jj * 4), Bp + jj * 4);
            CP_COMMIT();
            CP_WAIT(1);   // chunk kc landed
        } else {
            CP_WAIT(0);
        }
        __syncthreads();

        #pragma unroll
        for (int ks = 0; ks < 4; ks++) {
            const int kb = ks * 8;
            // A fragments: 4 m-tiles x 4 regs (cvt to tf32 at load)
            uint32_t af[4][4];
            #pragma unroll
            for (int mi = 0; mi < 4; mi++) {
                const int r = wm * 64 + mi * 16 + gid;
                af[mi][0] = rn_tf32(ASM(cur, r,     kb + tig    ));
                af[mi][1] = rn_tf32(ASM(cur, r + 8, kb + tig    ));
                af[mi][2] = rn_tf32(ASM(cur, r,     kb + tig + 4));
                af[mi][3] = rn_tf32(ASM(cur, r + 8, kb + tig + 4));
            }
            // B fragments: 4 n-tiles x 2 regs
            uint32_t bf[4][2];
            #pragma unroll
            for (int ni = 0; ni < 4; ni++) {
                const int c = wn * 32 + ni * 8 + gid;
                bf[ni][0] = rn_tf32(BSM(cur, kb + tig,     c));
                bf[ni][1] = rn_tf32(BSM(cur, kb + tig + 4, c));
            }
            #pragma unroll
            for (int mi = 0; mi < 4; mi++)
                #pragma unroll
                for (int ni = 0; ni < 4; ni++) {
                    asm volatile(
                        "mma.sync.aligned.m16n8k8.row.col.f32.tf32.tf32.f32 "
                        "{%0,%1,%2,%3}, {%4,%5,%6,%7}, {%8,%9}, {%0,%1,%2,%3};"
                        : "+f"(acc[mi][ni][0]), "+f"(acc[mi][ni][1]),
                          "+f"(acc[mi][ni][2]), "+f"(acc[mi][ni][3])
                        : "r"(af[mi][0]), "r"(af[mi][1]), "r"(af[mi][2]), "r"(af[mi][3]),
                          "r"(bf[ni][0]), "r"(bf[ni][1]));
                }
        }
        __syncthreads();
    }

    // Epilogue: + bias, float2 stores straight from fragments
    #pragma unroll
    for (int mi = 0; mi < 4; mi++) {
        const int r0 = m0 + wm * 64 + mi * 16 + gid;
        #pragma unroll
        for (int ni = 0; ni < 4; ni++) {
            const int c = n0 + wn * 32 + ni * 8 + tig * 2;
            const float2 bv = *(const float2*)(bias + c);
            float2 v0, v1;
            v0.x = acc[mi][ni][0] + bv.x;
            v0.y = acc[mi][ni][1] + bv.y;
            v1.x = acc[mi][ni][2] + bv.x;
            v1.y = acc[mi][ni][3] + bv.y;
            *(float2*)(C + (size_t)r0 * N + c)       = v0;
            *(float2*)(C + (size_t)(r0 + 8) * N + c) = v1;
        }
    }
    #undef ASM
    #undef BSM
}

// ===========================================================================
// Block reductions
// ===========================================================================
__device__ __forceinline__ float blockSumN(float v, float* red, int nw) {
    #pragma unroll
    for (int o = 16; o > 0; o >>= 1) v += __shfl_down_sync(0xffffffffu, v, o);
    const int lane = threadIdx.x & 31, w = threadIdx.x >> 5;
    if (lane == 0) red[w] = v;
    __syncthreads();
    if (w == 0) {
        v = (lane < nw) ? red[lane] : 0.f;
        #pragma unroll
        for (int o = 4; o > 0; o >>= 1) v += __shfl_down_sync(0xffffffffu, v, o);
        if (lane == 0) red[0] = v;
    }
    __syncthreads();
    float out = red[0];
    __syncthreads();
    return out;
}

__device__ __forceinline__ float blockMaxN(float v, float* red, int nw) {
    #pragma unroll
    for (int o = 16; o > 0; o >>= 1) v = fmaxf(v, __shfl_down_sync(0xffffffffu, v, o));
    const int lane = threadIdx.x & 31, w = threadIdx.x >> 5;
    if (lane == 0) red[w] = v;
    __syncthreads();
    if (w == 0) {
        v = (lane < nw) ? red[lane] : -INFINITY;
        #pragma unroll
        for (int o = 4; o > 0; o >>= 1) v = fmaxf(v, __shfl_down_sync(0xffffffffu, v, o));
        if (lane == 0) red[0] = v;
    }
    __syncthreads();
    float out = red[0];
    __syncthreads();
    return out;
}

// ===========================================================================
// One-pass LayerNorm + ReLU: block = H/4 threads, one float4 per thread
// ===========================================================================
__global__ void ln_relu_v2(float* __restrict__ x, const float* __restrict__ g,
                           const float* __restrict__ be)
{
    __shared__ float red[8];
    const int H = blockDim.x * 4;
    const int nw = blockDim.x >> 5;
    float4* xp = (float4*)(x + (size_t)blockIdx.x * H);
    float4 v = xp[threadIdx.x];

    float s  = v.x + v.y + v.z + v.w;
    float s2 = v.x * v.x + v.y * v.y + v.z * v.z + v.w * v.w;
    s  = blockSumN(s, red, nw);
    s2 = blockSumN(s2, red, nw);
    const float mu  = s / H;
    const float var = s2 / H - mu * mu;
    const float rs  = rsqrtf(var + 1e-5f);

    float4 gg = ((const float4*)g)[threadIdx.x];
    float4 bb = ((const float4*)be)[threadIdx.x];
    v.x = fmaxf((v.x - mu) * rs * gg.x + bb.x, 0.f);
    v.y = fmaxf((v.y - mu) * rs * gg.y + bb.y, 0.f);
    v.z = fmaxf((v.z - mu) * rs * gg.z + bb.z, 0.f);
    v.w = fmaxf((v.w - mu) * rs * gg.w + bb.w, 0.f);
    xp[threadIdx.x] = v;
}

// ===========================================================================
// Fused epilogue: softmax -> attn; W = Wflat*attn; Gram-Schmidt K=4; writes
// W_ortho [B,K,D] and attn [B,D]. One 256-thread block per row; vectors in regs.
// ===========================================================================
__global__ __launch_bounds__(256) void epilogue_kernel(
    const float* __restrict__ wflat, const float* __restrict__ logits,
    float* __restrict__ out)
{
    __shared__ float red[8];
    const int row = blockIdx.x;
    const int tid = threadIdx.x;
    constexpr int J = Dd / 256;  // 3

    float l[J];
    float m = -INFINITY;
    #pragma unroll
    for (int j = 0; j < J; j++) {
        l[j] = logits[(size_t)row * Dd + tid + j * 256];
        m = fmaxf(m, l[j]);
    }
    m = blockMaxN(m, red, 8);
    float e[J], s = 0.f;
    #pragma unroll
    for (int j = 0; j < J; j++) { e[j] = expf(l[j] - m); s += e[j]; }
    s = blockSumN(s, red, 8);
    const float inv_s = 1.f / s;
    float attn[J];
    float* out_attn = out + (size_t)Bsz * KD;
    #pragma unroll
    for (int j = 0; j < J; j++) {
        attn[j] = e[j] * inv_s;
        out_attn[(size_t)row * Dd + tid + j * 256] = attn[j];
    }

    float wv[Kk][J];
    #pragma unroll
    for (int k = 0; k < Kk; k++)
        #pragma unroll
        for (int j = 0; j < J; j++)
            wv[k][j] = wflat[(size_t)row * KD + k * Dd + tid + j * 256] * attn[j];

    #pragma unroll
    for (int k = 0; k < Kk; k++) {
        #pragma unroll
        for (int p = 0; p < k; p++) {
            float d = 0.f;
            #pragma unroll
            for (int j = 0; j < J; j++) d += wv[k][j] * wv[p][j];
            d = blockSumN(d, red, 8);
            #pragma unroll
            for (int j = 0; j < J; j++) wv[k][j] -= d * wv[p][j];
        }
        float n2 = 0.f;
        #pragma unroll
        for (int j = 0; j < J; j++) n2 += wv[k][j] * wv[k][j];
        n2 = blockSumN(n2, red, 8);
        const float inv = 1.f / fmaxf(sqrtf(n2), 1e-12f);
        #pragma unroll
        for (int j = 0; j < J; j++) {
            wv[k][j] *= inv;
            out[(size_t)row * KD + k * Dd + tid + j * 256] = wv[k][j];
        }
    }
}

// ===========================================================================
extern "C" void kernel_launch(void* const* d_in, const int* in_sizes, int n_in,
                              void* d_out, int out_size)
{
    const float* emb = (const float*)d_in[0];
    const float* W1  = (const float*)d_in[1];
    const float* b1  = (const float*)d_in[2];
    const float* g1  = (const float*)d_in[3];
    const float* be1 = (const float*)d_in[4];
    const float* W2  = (const float*)d_in[5];
    const float* b2  = (const float*)d_in[6];
    const float* g2  = (const float*)d_in[7];
    const float* be2 = (const float*)d_in[8];
    const float* Wd  = (const float*)d_in[9];
    const float* bd  = (const float*)d_in[10];
    const float* Wa  = (const float*)d_in[11];
    const float* ba  = (const float*)d_in[12];
    float* out = (float*)d_out;

    float *h1, *h2, *wflat, *logits;
    cudaGetSymbolAddress((void**)&h1, g_h1);
    cudaGetSymbolAddress((void**)&h2, g_h2);
    cudaGetSymbolAddress((void**)&wflat, g_wflat);
    cudaGetSymbolAddress((void**)&logits, g_logits);

    cudaFuncSetAttribute(mma_gemm, cudaFuncAttributeMaxDynamicSharedMemorySize,
                         GEMM_SMEM_BYTES);

    // Layer 1: emb[B,768] @ W1[768,512] + b1 -> LN -> relu
    mma_gemm<<<dim3(H1 / BN, Bsz / BM), 256, GEMM_SMEM_BYTES>>>(emb, W1, b1, h1, Bsz, H1, Dd);
    ln_relu_v2<<<Bsz, H1 / 4>>>(h1, g1, be1);
    // Layer 2: h1[B,512] @ W2[512,256] + b2 -> LN -> relu
    mma_gemm<<<dim3(H2 / BN, Bsz / BM), 256, GEMM_SMEM_BYTES>>>(h1, W2, b2, h2, Bsz, H2, H1);
    ln_relu_v2<<<Bsz, H2 / 4>>>(h2, g2, be2);
    // Heads
    mma_gemm<<<dim3(KD / BN, Bsz / BM), 256, GEMM_SMEM_BYTES>>>(h2, Wd, bd, wflat, Bsz, KD, H2);
    mma_gemm<<<dim3(Dd / BN, Bsz / BM), 256, GEMM_SMEM_BYTES>>>(h2, Wa, ba, logits, Bsz, Dd, H2);
    // softmax + modulate + Gram-Schmidt
    epilogue_kernel<<<Bsz, 256>>>(wflat, logits, out);
}

// round 6
// speedup vs baseline: 2.0147x; 1.0992x over previous
#include <cuda_runtime.h>
#include <cuda_bf16.h>
#include <math.h>
#include <cstdint>

// Problem dims (compile-time)
static constexpr int Bsz = 16384;
static constexpr int Dd  = 768;
static constexpr int Kk  = 4;
static constexpr int H1  = 512;
static constexpr int H2  = 256;
static constexpr int KD  = Kk * Dd;   // 3072

// Scratch (device globals: allocation-free per harness rules)
__device__ float g_h1[Bsz * H1];
__device__ float g_h2[Bsz * H2];
__device__ float g_wflat[Bsz * KD];
__device__ float g_logits[Bsz * Dd];

__device__ __forceinline__ uint32_t smem_u32(const void* p) {
    uint32_t a;
    asm("{ .reg .u64 t; cvta.to.shared.u64 t, %1; cvt.u32.u64 %0, t; }"
        : "=r"(a) : "l"(p));
    return a;
}

__device__ __forceinline__ void cp_async16(void* dst, const void* src) {
    asm volatile("cp.async.cg.shared.global [%0], [%1], 16;"
                 :: "r"(smem_u32(dst)), "l"(src) : "memory");
}
#define CP_COMMIT() asm volatile("cp.async.commit_group;" ::: "memory")
#define CP_WAIT(n)  asm volatile("cp.async.wait_group %0;" :: "n"(n) : "memory")

// pack two fp32 -> one f16x2 register ({lo, hi}), round-to-nearest
__device__ __forceinline__ uint32_t pack_f16x2(float lo, float hi) {
    uint32_t d;
    asm("cvt.rn.f16x2.f32 %0, %1, %2;" : "=r"(d) : "f"(hi), "f"(lo));
    return d;
}

// ===========================================================================
// FP16 mma.sync GEMM (m16n8k16, fp32 accumulate), cp.async double-buffered.
// C[M,N] = A[M,K] @ B[K,N] + bias[N]
// BM=128, BN=128, BK=32. 256 threads = 8 warps in 2x4 (m x n) grid.
// Warp tile 64x32 = 4x4 mma tiles of m16n8k16.
// fp32 tiles in smem; fp32->fp16 conversion at fragment load.
// Requires M%128==0, N%128==0, K%32==0 (true for all 4 GEMMs).
// ===========================================================================
#define BM 128
#define BN 128
#define BKt 32

// smem pads for conflict-free fragment loads with paired-k (fp16) accesses:
//  A stride 40 (=8 mod 32): float2 load banks (8*gid + 2*tig) distinct/phase
//  B stride 132 (=4 mod 16): scalar load banks (8*tig + gid) distinct
static constexpr int AS_STRIDE = 40;
static constexpr int BS_STRIDE = 132;
static constexpr int AS_ELEMS  = BM * AS_STRIDE;    // 5120 floats / buffer
static constexpr int BS_ELEMS  = BKt * BS_STRIDE;   // 4224 floats / buffer
static constexpr int GEMM_SMEM_BYTES = (2 * AS_ELEMS + 2 * BS_ELEMS) * 4;  // 74752

__global__ __launch_bounds__(256, 2) void mma_gemm(
    const float* __restrict__ A, const float* __restrict__ B,
    const float* __restrict__ bias, float* __restrict__ C,
    int M, int N, int Kdim)
{
    extern __shared__ float smem[];
    float* AsBuf[2] = { smem, smem + AS_ELEMS };
    float* BsBuf[2] = { smem + 2 * AS_ELEMS, smem + 2 * AS_ELEMS + BS_ELEMS };
    #define ASM(b, r, c) AsBuf[b][(r) * AS_STRIDE + (c)]
    #define BSM(b, r, c) BsBuf[b][(r) * BS_STRIDE + (c)]

    const int tid  = threadIdx.x;
    const int lane = tid & 31;
    const int w    = tid >> 5;
    const int wm   = w >> 2;          // 0..1
    const int wn   = w & 3;           // 0..3
    const int gid  = lane >> 2;       // 0..7
    const int tig  = lane & 3;        // 0..3

    const int m0 = blockIdx.y * BM;
    const int n0 = blockIdx.x * BN;

    // global->smem mapping (16 floats per thread per tile, 4x 16B cp.async)
    const int aRow = tid >> 1;              // 0..127
    const int aK0  = (tid & 1) * 16;        // 0 or 16
    const int bRow = tid & 31;              // 0..31 (conflict-free store phases)
    const int bC0  = (tid >> 5) * 16;       // 0..112

    const float* ApBase = A + (size_t)(m0 + aRow) * Kdim + aK0;
    const float* BpBase = B + (size_t)bRow * N + n0 + bC0;

    float acc[4][4][4];
    #pragma unroll
    for (int i = 0; i < 4; i++)
        #pragma unroll
        for (int j = 0; j < 4; j++)
            #pragma unroll
            for (int r = 0; r < 4; r++) acc[i][j][r] = 0.f;

    const int nch = Kdim / BKt;

    // prologue: stage chunk 0 into buffer 0
    {
        #pragma unroll
        for (int jj = 0; jj < 4; jj++)
            cp_async16(&ASM(0, aRow, aK0 + jj * 4), ApBase + jj * 4);
        #pragma unroll
        for (int jj = 0; jj < 4; jj++)
            cp_async16(&BSM(0, bRow, bC0 + jj * 4), BpBase + jj * 4);
        CP_COMMIT();
    }

    for (int kc = 0; kc < nch; kc++) {
        const int cur = kc & 1;
        if (kc + 1 < nch) {
            const int nxt = cur ^ 1;
            const float* Ap = ApBase + (kc + 1) * BKt;
            const float* Bp = BpBase + (size_t)(kc + 1) * BKt * N;
            #pragma unroll
            for (int jj = 0; jj < 4; jj++)
                cp_async16(&ASM(nxt, aRow, aK0 + jj * 4), Ap + jj * 4);
            #pragma unroll
            for (int jj = 0; jj < 4; jj++)
                cp_async16(&BSM(nxt, bRow, bC0 + jj * 4), Bp + jj * 4);
            CP_COMMIT();
            CP_WAIT(1);   // chunk kc landed
        } else {
            CP_WAIT(0);
        }
        __syncthreads();

        #pragma unroll
        for (int ks = 0; ks < 2; ks++) {       // 2 k-steps of depth 16
            const int kb = ks * 16;
            const int kA = kb + 2 * tig;       // A/B k base for this thread
            // A fragments: 4 m-tiles x 4 f16x2 regs (float2 LDS + pack)
            uint32_t af[4][4];
            #pragma unroll
            for (int mi = 0; mi < 4; mi++) {
                const int r = wm * 64 + mi * 16 + gid;
                float2 p0 = *(const float2*)&ASM(cur, r,     kA    );
                float2 p1 = *(const float2*)&ASM(cur, r + 8, kA    );
                float2 p2 = *(const float2*)&ASM(cur, r,     kA + 8);
                float2 p3 = *(const float2*)&ASM(cur, r + 8, kA + 8);
                af[mi][0] = pack_f16x2(p0.x, p0.y);
                af[mi][1] = pack_f16x2(p1.x, p1.y);
                af[mi][2] = pack_f16x2(p2.x, p2.y);
                af[mi][3] = pack_f16x2(p3.x, p3.y);
            }
            // B fragments: 4 n-tiles x 2 f16x2 regs (2 scalar LDS + pack each)
            uint32_t bf[4][2];
            #pragma unroll
            for (int ni = 0; ni < 4; ni++) {
                const int c = wn * 32 + ni * 8 + gid;
                bf[ni][0] = pack_f16x2(BSM(cur, kA,     c), BSM(cur, kA + 1, c));
                bf[ni][1] = pack_f16x2(BSM(cur, kA + 8, c), BSM(cur, kA + 9, c));
            }
            #pragma unroll
            for (int mi = 0; mi < 4; mi++)
                #pragma unroll
                for (int ni = 0; ni < 4; ni++) {
                    asm volatile(
                        "mma.sync.aligned.m16n8k16.row.col.f32.f16.f16.f32 "
                        "{%0,%1,%2,%3}, {%4,%5,%6,%7}, {%8,%9}, {%0,%1,%2,%3};"
                        : "+f"(acc[mi][ni][0]), "+f"(acc[mi][ni][1]),
                          "+f"(acc[mi][ni][2]), "+f"(acc[mi][ni][3])
                        : "r"(af[mi][0]), "r"(af[mi][1]), "r"(af[mi][2]), "r"(af[mi][3]),
                          "r"(bf[ni][0]), "r"(bf[ni][1]));
                }
        }
        __syncthreads();
    }

    // Epilogue: + bias, float2 stores straight from fragments
    #pragma unroll
    for (int mi = 0; mi < 4; mi++) {
        const int r0 = m0 + wm * 64 + mi * 16 + gid;
        #pragma unroll
        for (int ni = 0; ni < 4; ni++) {
            const int c = n0 + wn * 32 + ni * 8 + tig * 2;
            const float2 bv = *(const float2*)(bias + c);
            float2 v0, v1;
            v0.x = acc[mi][ni][0] + bv.x;
            v0.y = acc[mi][ni][1] + bv.y;
            v1.x = acc[mi][ni][2] + bv.x;
            v1.y = acc[mi][ni][3] + bv.y;
            *(float2*)(C + (size_t)r0 * N + c)       = v0;
            *(float2*)(C + (size_t)(r0 + 8) * N + c) = v1;
        }
    }
    #undef ASM
    #undef BSM
}

// ===========================================================================
// Block reductions
// ===========================================================================
__device__ __forceinline__ float blockSumN(float v, float* red, int nw) {
    #pragma unroll
    for (int o = 16; o > 0; o >>= 1) v += __shfl_down_sync(0xffffffffu, v, o);
    const int lane = threadIdx.x & 31, w = threadIdx.x >> 5;
    if (lane == 0) red[w] = v;
    __syncthreads();
    if (w == 0) {
        v = (lane < nw) ? red[lane] : 0.f;
        #pragma unroll
        for (int o = 4; o > 0; o >>= 1) v += __shfl_down_sync(0xffffffffu, v, o);
        if (lane == 0) red[0] = v;
    }
    __syncthreads();
    float out = red[0];
    __syncthreads();
    return out;
}

__device__ __forceinline__ float blockMaxN(float v, float* red, int nw) {
    #pragma unroll
    for (int o = 16; o > 0; o >>= 1) v = fmaxf(v, __shfl_down_sync(0xffffffffu, v, o));
    const int lane = threadIdx.x & 31, w = threadIdx.x >> 5;
    if (lane == 0) red[w] = v;
    __syncthreads();
    if (w == 0) {
        v = (lane < nw) ? red[lane] : -INFINITY;
        #pragma unroll
        for (int o = 4; o > 0; o >>= 1) v = fmaxf(v, __shfl_down_sync(0xffffffffu, v, o));
        if (lane == 0) red[0] = v;
    }
    __syncthreads();
    float out = red[0];
    __syncthreads();
    return out;
}

// ===========================================================================
// One-pass LayerNorm + ReLU: block = H/4 threads, one float4 per thread
// ===========================================================================
__global__ void ln_relu_v2(float* __restrict__ x, const float* __restrict__ g,
                           const float* __restrict__ be)
{
    __shared__ float red[8];
    const int H = blockDim.x * 4;
    const int nw = blockDim.x >> 5;
    float4* xp = (float4*)(x + (size_t)blockIdx.x * H);
    float4 v = xp[threadIdx.x];

    float s  = v.x + v.y + v.z + v.w;
    float s2 = v.x * v.x + v.y * v.y + v.z * v.z + v.w * v.w;
    s  = blockSumN(s, red, nw);
    s2 = blockSumN(s2, red, nw);
    const float mu  = s / H;
    const float var = s2 / H - mu * mu;
    const float rs  = rsqrtf(var + 1e-5f);

    float4 gg = ((const float4*)g)[threadIdx.x];
    float4 bb = ((const float4*)be)[threadIdx.x];
    v.x = fmaxf((v.x - mu) * rs * gg.x + bb.x, 0.f);
    v.y = fmaxf((v.y - mu) * rs * gg.y + bb.y, 0.f);
    v.z = fmaxf((v.z - mu) * rs * gg.z + bb.z, 0.f);
    v.w = fmaxf((v.w - mu) * rs * gg.w + bb.w, 0.f);
    xp[threadIdx.x] = v;
}

// ===========================================================================
// Fused epilogue: softmax -> attn; W = Wflat*attn; Gram-Schmidt K=4; writes
// W_ortho [B,K,D] and attn [B,D]. One 256-thread block per row; vectors in regs.
// ===========================================================================
__global__ __launch_bounds__(256) void epilogue_kernel(
    const float* __restrict__ wflat, const float* __restrict__ logits,
    float* __restrict__ out)
{
    __shared__ float red[8];
    const int row = blockIdx.x;
    const int tid = threadIdx.x;
    constexpr int J = Dd / 256;  // 3

    float l[J];
    float m = -INFINITY;
    #pragma unroll
    for (int j = 0; j < J; j++) {
        l[j] = logits[(size_t)row * Dd + tid + j * 256];
        m = fmaxf(m, l[j]);
    }
    m = blockMaxN(m, red, 8);
    float e[J], s = 0.f;
    #pragma unroll
    for (int j = 0; j < J; j++) { e[j] = expf(l[j] - m); s += e[j]; }
    s = blockSumN(s, red, 8);
    const float inv_s = 1.f / s;
    float attn[J];
    float* out_attn = out + (size_t)Bsz * KD;
    #pragma unroll
    for (int j = 0; j < J; j++) {
        attn[j] = e[j] * inv_s;
        out_attn[(size_t)row * Dd + tid + j * 256] = attn[j];
    }

    float wv[Kk][J];
    #pragma unroll
    for (int k = 0; k < Kk; k++)
        #pragma unroll
        for (int j = 0; j < J; j++)
            wv[k][j] = wflat[(size_t)row * KD + k * Dd + tid + j * 256] * attn[j];

    #pragma unroll
    for (int k = 0; k < Kk; k++) {
        #pragma unroll
        for (int p = 0; p < k; p++) {
            float d = 0.f;
            #pragma unroll
            for (int j = 0; j < J; j++) d += wv[k][j] * wv[p][j];
            d = blockSumN(d, red, 8);
            #pragma unroll
            for (int j = 0; j < J; j++) wv[k][j] -= d * wv[p][j];
        }
        float n2 = 0.f;
        #pragma unroll
        for (int j = 0; j < J; j++) n2 += wv[k][j] * wv[k][j];
        n2 = blockSumN(n2, red, 8);
        const float inv = 1.f / fmaxf(sqrtf(n2), 1e-12f);
        #pragma unroll
        for (int j = 0; j < J; j++) {
            wv[k][j] *= inv;
            out[(size_t)row * KD + k * Dd + tid + j * 256] = wv[k][j];
        }
    }
}

// ===========================================================================
extern "C" void kernel_launch(void* const* d_in, const int* in_sizes, int n_in,
                              void* d_out, int out_size)
{
    const float* emb = (const float*)d_in[0];
    const float* W1  = (const float*)d_in[1];
    const float* b1  = (const float*)d_in[2];
    const float* g1  = (const float*)d_in[3];
    const float* be1 = (const float*)d_in[4];
    const float* W2  = (const float*)d_in[5];
    const float* b2  = (const float*)d_in[6];
    const float* g2  = (const float*)d_in[7];
    const float* be2 = (const float*)d_in[8];
    const float* Wd  = (const float*)d_in[9];
    const float* bd  = (const float*)d_in[10];
    const float* Wa  = (const float*)d_in[11];
    const float* ba  = (const float*)d_in[12];
    float* out = (float*)d_out;

    float *h1, *h2, *wflat, *logits;
    cudaGetSymbolAddress((void**)&h1, g_h1);
    cudaGetSymbolAddress((void**)&h2, g_h2);
    cudaGetSymbolAddress((void**)&wflat, g_wflat);
    cudaGetSymbolAddress((void**)&logits, g_logits);

    cudaFuncSetAttribute(mma_gemm, cudaFuncAttributeMaxDynamicSharedMemorySize,
                         GEMM_SMEM_BYTES);

    // Layer 1: emb[B,768] @ W1[768,512] + b1 -> LN -> relu
    mma_gemm<<<dim3(H1 / BN, Bsz / BM), 256, GEMM_SMEM_BYTES>>>(emb, W1, b1, h1, Bsz, H1, Dd);
    ln_relu_v2<<<Bsz, H1 / 4>>>(h1, g1, be1);
    // Layer 2: h1[B,512] @ W2[512,256] + b2 -> LN -> relu
    mma_gemm<<<dim3(H2 / BN, Bsz / BM), 256, GEMM_SMEM_BYTES>>>(h1, W2, b2, h2, Bsz, H2, H1);
    ln_relu_v2<<<Bsz, H2 / 4>>>(h2, g2, be2);
    // Heads
    mma_gemm<<<dim3(KD / BN, Bsz / BM), 256, GEMM_SMEM_BYTES>>>(h2, Wd, bd, wflat, Bsz, KD, H2);
    mma_gemm<<<dim3(Dd / BN, Bsz / BM), 256, GEMM_SMEM_BYTES>>>(h2, Wa, ba, logits, Bsz, Dd, H2);
    // softmax + modulate + Gram-Schmidt
    epilogue_kernel<<<Bsz, 256>>>(wflat, logits, out);
}

// round 7
// speedup vs baseline: 3.6551x; 1.8142x over previous
#include <cuda_runtime.h>
#include <cuda_fp16.h>
#include <math.h>
#include <cstdint>

// Problem dims (compile-time)
static constexpr int Bsz = 16384;
static constexpr int Dd  = 768;
static constexpr int Kk  = 4;
static constexpr int H1  = 512;
static constexpr int H2  = 256;
static constexpr int KD  = Kk * Dd;   // 3072

// Scratch (device globals: allocation-free per harness rules)
__device__ float  g_h1[Bsz * H1];
__device__ float  g_h2[Bsz * H2];
__device__ float  g_wflat[Bsz * KD];
__device__ float  g_logits[Bsz * Dd];
__device__ __half g_embh[Bsz * Dd];
__device__ __half g_h1h[Bsz * H1];
__device__ __half g_h2h[Bsz * H2];
__device__ __half g_W1h[Dd * H1];
__device__ __half g_W2h[H1 * H2];
__device__ __half g_Wdh[H2 * KD];
__device__ __half g_Wah[H2 * Dd];

__device__ __forceinline__ uint32_t smem_u32(const void* p) {
    uint32_t a;
    asm("{ .reg .u64 t; cvta.to.shared.u64 t, %1; cvt.u32.u64 %0, t; }"
        : "=r"(a) : "l"(p));
    return a;
}

__device__ __forceinline__ void cp_async16(uint32_t dst, const void* src) {
    asm volatile("cp.async.cg.shared.global [%0], [%1], 16;"
                 :: "r"(dst), "l"(src) : "memory");
}
#define CP_COMMIT() asm volatile("cp.async.commit_group;" ::: "memory")
#define CP_WAIT(n)  asm volatile("cp.async.wait_group %0;" :: "n"(n) : "memory")

// ===========================================================================
// FP16 mma GEMM, classic Ampere-style: fp16 gmem -> cp.async -> fp16 smem
// -> ldmatrix(.trans) -> m16n8k16 (fp32 accum).
// C[M,N] = A[M,K] @ B[K,N] + bias[N]
// BM=128, BN=128, BK=32. 256 threads = 8 warps in 2x4 (m x n) grid.
// Warp tile 64x32 = 4x4 mma tiles. Requires M%128, N%128, K%32 == 0.
// ===========================================================================
#define BM 128
#define BN 128
#define BKt 32

// Pad strides chosen so all 8 ldmatrix row-addresses per phase hit distinct
// 16B bank groups:
//  A: 40 halves = 80 B/row: 80*r mod 128 = {0,80,32,112,64,16,96,48} distinct
//  B: 136 halves = 272 B/row: 272*k mod 128 = 16*k distinct
static constexpr int AS_STRIDE = 40;    // halves
static constexpr int BS_STRIDE = 136;   // halves
static constexpr int AS_ELEMS  = BM * AS_STRIDE;   // 5120 halves
static constexpr int BS_ELEMS  = BKt * BS_STRIDE;  // 4352 halves

__global__ __launch_bounds__(256, 2) void mma_gemm(
    const __half* __restrict__ A, const __half* __restrict__ B,
    const float* __restrict__ bias, float* __restrict__ C,
    int M, int N, int Kdim)
{
    __shared__ __half Asm[2][AS_ELEMS];
    __shared__ __half Bsm[2][BS_ELEMS];

    const int tid  = threadIdx.x;
    const int lane = tid & 31;
    const int w    = tid >> 5;
    const int wm   = w >> 2;          // 0..1
    const int wn   = w & 3;           // 0..3
    const int gid  = lane >> 2;       // 0..7
    const int tig  = lane & 3;        // 0..3

    const int m0 = blockIdx.y * BM;
    const int n0 = blockIdx.x * BN;

    // cp.async segment mapping (16B = 8 halves per op, 2 iters each tile)
    // A tile 128 x 32 halves: 4 segs/row -> 512 segs
    // B tile 32 x 128 halves: 16 segs/row -> 512 segs
    const uint32_t asm0 = smem_u32(&Asm[0][0]);
    const uint32_t asm1 = smem_u32(&Asm[1][0]);
    const uint32_t bsm0 = smem_u32(&Bsm[0][0]);
    const uint32_t bsm1 = smem_u32(&Bsm[1][0]);

    float acc[4][4][4];
    #pragma unroll
    for (int i = 0; i < 4; i++)
        #pragma unroll
        for (int j = 0; j < 4; j++)
            #pragma unroll
            for (int r = 0; r < 4; r++) acc[i][j][r] = 0.f;

    const int nch = Kdim / BKt;

    // stage a chunk into buffer buf
    auto stage = [&](int kc, uint32_t abuf, uint32_t bbuf) {
        #pragma unroll
        for (int it = 0; it < 2; it++) {
            int sid = tid + it * 256;
            int ar = sid >> 2, aseg = sid & 2 + (sid & 1);  // (placeholder, fixed below)
        }
    };
    // (lambda above unused; explicit code below for clarity)

    {   // prologue: chunk 0 -> buffer 0
        #pragma unroll
        for (int it = 0; it < 2; it++) {
            int sid = tid + it * 256;
            int ar = sid >> 2, as = sid & 3;
            cp_async16(asm0 + (ar * AS_STRIDE + as * 8) * 2,
                       A + (size_t)(m0 + ar) * Kdim + as * 8);
            int br = sid >> 4, bs = sid & 15;
            cp_async16(bsm0 + (br * BS_STRIDE + bs * 8) * 2,
                       B + (size_t)br * N + n0 + bs * 8);
        }
        CP_COMMIT();
    }

    for (int kc = 0; kc < nch; kc++) {
        const int cur = kc & 1;
        const uint32_t aCur = cur ? asm1 : asm0;
        const uint32_t bCur = cur ? bsm1 : bsm0;
        if (kc + 1 < nch) {
            const uint32_t aNxt = cur ? asm0 : asm1;
            const uint32_t bNxt = cur ? bsm0 : bsm1;
            const int k0 = (kc + 1) * BKt;
            #pragma unroll
            for (int it = 0; it < 2; it++) {
                int sid = tid + it * 256;
                int ar = sid >> 2, as = sid & 3;
                cp_async16(aNxt + (ar * AS_STRIDE + as * 8) * 2,
                           A + (size_t)(m0 + ar) * Kdim + k0 + as * 8);
                int br = sid >> 4, bs = sid & 15;
                cp_async16(bNxt + (br * BS_STRIDE + bs * 8) * 2,
                           B + (size_t)(k0 + br) * N + n0 + bs * 8);
            }
            CP_COMMIT();
            CP_WAIT(1);
        } else {
            CP_WAIT(0);
        }
        __syncthreads();

        #pragma unroll
        for (int ks = 0; ks < 2; ks++) {
            const int kb = ks * 16;   // k offset in halves
            // A fragments: 4 m-tiles via ldmatrix.x4
            uint32_t af[4][4];
            #pragma unroll
            for (int mi = 0; mi < 4; mi++) {
                const int r = wm * 64 + mi * 16;
                uint32_t addr = aCur
                    + (uint32_t)(r + (lane & 15)) * (AS_STRIDE * 2)
                    + kb * 2 + (lane >> 4) * 16;
                asm volatile(
                    "ldmatrix.sync.aligned.m8n8.x4.shared.b16 {%0,%1,%2,%3}, [%4];"
                    : "=r"(af[mi][0]), "=r"(af[mi][1]),
                      "=r"(af[mi][2]), "=r"(af[mi][3]) : "r"(addr));
            }
            // B fragments: 2 ldmatrix.x4.trans cover 4 n-tiles (16 cols each)
            uint32_t bf[4][2];
            #pragma unroll
            for (int nj = 0; nj < 2; nj++) {
                const int c = wn * 32 + nj * 16;
                uint32_t addr = bCur
                    + (uint32_t)(kb + ((lane >> 3) & 1) * 8 + (lane & 7)) * (BS_STRIDE * 2)
                    + (uint32_t)(c + (lane >> 4) * 8) * 2;
                asm volatile(
                    "ldmatrix.sync.aligned.m8n8.x4.trans.shared.b16 {%0,%1,%2,%3}, [%4];"
                    : "=r"(bf[nj * 2][0]), "=r"(bf[nj * 2][1]),
                      "=r"(bf[nj * 2 + 1][0]), "=r"(bf[nj * 2 + 1][1]) : "r"(addr));
            }
            #pragma unroll
            for (int mi = 0; mi < 4; mi++)
                #pragma unroll
                for (int ni = 0; ni < 4; ni++) {
                    asm volatile(
                        "mma.sync.aligned.m16n8k16.row.col.f32.f16.f16.f32 "
                        "{%0,%1,%2,%3}, {%4,%5,%6,%7}, {%8,%9}, {%0,%1,%2,%3};"
                        : "+f"(acc[mi][ni][0]), "+f"(acc[mi][ni][1]),
                          "+f"(acc[mi][ni][2]), "+f"(acc[mi][ni][3])
                        : "r"(af[mi][0]), "r"(af[mi][1]), "r"(af[mi][2]), "r"(af[mi][3]),
                          "r"(bf[ni][0]), "r"(bf[ni][1]));
                }
        }
        __syncthreads();
    }

    // Epilogue: + bias, float2 stores straight from fragments
    #pragma unroll
    for (int mi = 0; mi < 4; mi++) {
        const int r0 = m0 + wm * 64 + mi * 16 + gid;
        #pragma unroll
        for (int ni = 0; ni < 4; ni++) {
            const int c = n0 + wn * 32 + ni * 8 + tig * 2;
            const float2 bv = *(const float2*)(bias + c);
            float2 v0, v1;
            v0.x = acc[mi][ni][0] + bv.x;
            v0.y = acc[mi][ni][1] + bv.y;
            v1.x = acc[mi][ni][2] + bv.x;
            v1.y = acc[mi][ni][3] + bv.y;
            *(float2*)(C + (size_t)r0 * N + c)       = v0;
            *(float2*)(C + (size_t)(r0 + 8) * N + c) = v1;
        }
    }
}

// ===========================================================================
// fp32 -> fp16 convert (rn), vectorized
// ===========================================================================
__global__ void f32_to_f16_k(const float* __restrict__ s, __half* __restrict__ d,
                             int n)
{
    int i = (blockIdx.x * blockDim.x + threadIdx.x) * 4;
    if (i < n) {
        float4 v = *(const float4*)(s + i);
        __half2* p = (__half2*)(d + i);
        p[0] = __floats2half2_rn(v.x, v.y);
        p[1] = __floats2half2_rn(v.z, v.w);
    }
}

// ===========================================================================
// Block reductions
// ===========================================================================
__device__ __forceinline__ float blockSumN(float v, float* red, int nw) {
    #pragma unroll
    for (int o = 16; o > 0; o >>= 1) v += __shfl_down_sync(0xffffffffu, v, o);
    const int lane = threadIdx.x & 31, w = threadIdx.x >> 5;
    if (lane == 0) red[w] = v;
    __syncthreads();
    if (w == 0) {
        v = (lane < nw) ? red[lane] : 0.f;
        #pragma unroll
        for (int o = 4; o > 0; o >>= 1) v += __shfl_down_sync(0xffffffffu, v, o);
        if (lane == 0) red[0] = v;
    }
    __syncthreads();
    float out = red[0];
    __syncthreads();
    return out;
}

__device__ __forceinline__ float blockMaxN(float v, float* red, int nw) {
    #pragma unroll
    for (int o = 16; o > 0; o >>= 1) v = fmaxf(v, __shfl_down_sync(0xffffffffu, v, o));
    const int lane = threadIdx.x & 31, w = threadIdx.x >> 5;
    if (lane == 0) red[w] = v;
    __syncthreads();
    if (w == 0) {
        v = (lane < nw) ? red[lane] : -INFINITY;
        #pragma unroll
        for (int o = 4; o > 0; o >>= 1) v = fmaxf(v, __shfl_down_sync(0xffffffffu, v, o));
        if (lane == 0) red[0] = v;
    }
    __syncthreads();
    float out = red[0];
    __syncthreads();
    return out;
}

// ===========================================================================
// One-pass LayerNorm + ReLU; writes fp32 in place + fp16 shadow for next GEMM
// ===========================================================================
__global__ void ln_relu_v2h(float* __restrict__ x, const float* __restrict__ g,
                            const float* __restrict__ be, __half* __restrict__ xh)
{
    __shared__ float red[8];
    const int H = blockDim.x * 4;
    const int nw = blockDim.x >> 5;
    float4* xp = (float4*)(x + (size_t)blockIdx.x * H);
    __half2* hp = (__half2*)(xh + (size_t)blockIdx.x * H);
    float4 v = xp[threadIdx.x];

    float s  = v.x + v.y + v.z + v.w;
    float s2 = v.x * v.x + v.y * v.y + v.z * v.z + v.w * v.w;
    s  = blockSumN(s, red, nw);
    s2 = blockSumN(s2, red, nw);
    const float mu  = s / H;
    const float var = s2 / H - mu * mu;
    const float rs  = rsqrtf(var + 1e-5f);

    float4 gg = ((const float4*)g)[threadIdx.x];
    float4 bb = ((const float4*)be)[threadIdx.x];
    v.x = fmaxf((v.x - mu) * rs * gg.x + bb.x, 0.f);
    v.y = fmaxf((v.y - mu) * rs * gg.y + bb.y, 0.f);
    v.z = fmaxf((v.z - mu) * rs * gg.z + bb.z, 0.f);
    v.w = fmaxf((v.w - mu) * rs * gg.w + bb.w, 0.f);
    xp[threadIdx.x] = v;
    hp[threadIdx.x * 2]     = __floats2half2_rn(v.x, v.y);
    hp[threadIdx.x * 2 + 1] = __floats2half2_rn(v.z, v.w);
}

// ===========================================================================
// Fused epilogue: softmax -> attn; W = Wflat*attn; Gram-Schmidt K=4; writes
// W_ortho [B,K,D] and attn [B,D]. One 256-thread block per row; vectors in regs.
// ===========================================================================
__global__ __launch_bounds__(256) void epilogue_kernel(
    const float* __restrict__ wflat, const float* __restrict__ logits,
    float* __restrict__ out)
{
    __shared__ float red[8];
    const int row = blockIdx.x;
    const int tid = threadIdx.x;
    constexpr int J = Dd / 256;  // 3

    float l[J];
    float m = -INFINITY;
    #pragma unroll
    for (int j = 0; j < J; j++) {
        l[j] = logits[(size_t)row * Dd + tid + j * 256];
        m = fmaxf(m, l[j]);
    }
    m = blockMaxN(m, red, 8);
    float e[J], s = 0.f;
    #pragma unroll
    for (int j = 0; j < J; j++) { e[j] = expf(l[j] - m); s += e[j]; }
    s = blockSumN(s, red, 8);
    const float inv_s = 1.f / s;
    float attn[J];
    float* out_attn = out + (size_t)Bsz * KD;
    #pragma unroll
    for (int j = 0; j < J; j++) {
        attn[j] = e[j] * inv_s;
        out_attn[(size_t)row * Dd + tid + j * 256] = attn[j];
    }

    float wv[Kk][J];
    #pragma unroll
    for (int k = 0; k < Kk; k++)
        #pragma unroll
        for (int j = 0; j < J; j++)
            wv[k][j] = wflat[(size_t)row * KD + k * Dd + tid + j * 256] * attn[j];

    #pragma unroll
    for (int k = 0; k < Kk; k++) {
        #pragma unroll
        for (int p = 0; p < k; p++) {
            float d = 0.f;
            #pragma unroll
            for (int j = 0; j < J; j++) d += wv[k][j] * wv[p][j];
            d = blockSumN(d, red, 8);
            #pragma unroll
            for (int j = 0; j < J; j++) wv[k][j] -= d * wv[p][j];
        }
        float n2 = 0.f;
        #pragma unroll
        for (int j = 0; j < J; j++) n2 += wv[k][j] * wv[k][j];
        n2 = blockSumN(n2, red, 8);
        const float inv = 1.f / fmaxf(sqrtf(n2), 1e-12f);
        #pragma unroll
        for (int j = 0; j < J; j++) {
            wv[k][j] *= inv;
            out[(size_t)row * KD + k * Dd + tid + j * 256] = wv[k][j];
        }
    }
}

// ===========================================================================
extern "C" void kernel_launch(void* const* d_in, const int* in_sizes, int n_in,
                              void* d_out, int out_size)
{
    const float* emb = (const float*)d_in[0];
    const float* W1  = (const float*)d_in[1];
    const float* b1  = (const float*)d_in[2];
    const float* g1  = (const float*)d_in[3];
    const float* be1 = (const float*)d_in[4];
    const float* W2  = (const float*)d_in[5];
    const float* b2  = (const float*)d_in[6];
    const float* g2  = (const float*)d_in[7];
    const float* be2 = (const float*)d_in[8];
    const float* Wd  = (const float*)d_in[9];
    const float* bd  = (const float*)d_in[10];
    const float* Wa  = (const float*)d_in[11];
    const float* ba  = (const float*)d_in[12];
    float* out = (float*)d_out;

    float *h1, *h2, *wflat, *logits;
    __half *embh, *h1h, *h2h, *W1h, *W2h, *Wdh, *Wah;
    cudaGetSymbolAddress((void**)&h1, g_h1);
    cudaGetSymbolAddress((void**)&h2, g_h2);
    cudaGetSymbolAddress((void**)&wflat, g_wflat);
    cudaGetSymbolAddress((void**)&logits, g_logits);
    cudaGetSymbolAddress((void**)&embh, g_embh);
    cudaGetSymbolAddress((void**)&h1h, g_h1h);
    cudaGetSymbolAddress((void**)&h2h, g_h2h);
    cudaGetSymbolAddress((void**)&W1h, g_W1h);
    cudaGetSymbolAddress((void**)&W2h, g_W2h);
    cudaGetSymbolAddress((void**)&Wdh, g_Wdh);
    cudaGetSymbolAddress((void**)&Wah, g_Wah);

    auto cvt = [&](const float* s, __half* d, int n) {
        f32_to_f16_k<<<(n / 4 + 255) / 256, 256>>>(s, d, n);
    };
    cvt(emb, embh, Bsz * Dd);
    cvt(W1, W1h, Dd * H1);
    cvt(W2, W2h, H1 * H2);
    cvt(Wd, Wdh, H2 * KD);
    cvt(Wa, Wah, H2 * Dd);

    // Layer 1: emb[B,768] @ W1[768,512] + b1 -> LN -> relu (+fp16 shadow)
    mma_gemm<<<dim3(H1 / BN, Bsz / BM), 256>>>(embh, W1h, b1, h1, Bsz, H1, Dd);
    ln_relu_v2h<<<Bsz, H1 / 4>>>(h1, g1, be1, h1h);
    // Layer 2
    mma_gemm<<<dim3(H2 / BN, Bsz / BM), 256>>>(h1h, W2h, b2, h2, Bsz, H2, H1);
    ln_relu_v2h<<<Bsz, H2 / 4>>>(h2, g2, be2, h2h);
    // Heads
    mma_gemm<<<dim3(KD / BN, Bsz / BM), 256>>>(h2h, Wdh, bd, wflat, Bsz, KD, H2);
    mma_gemm<<<dim3(Dd / BN, Bsz / BM), 256>>>(h2h, Wah, ba, logits, Bsz, Dd, H2);
    // softmax + modulate + Gram-Schmidt
    epilogue_kernel<<<Bsz, 256>>>(wflat, logits, out);
}

// round 9
// speedup vs baseline: 3.7328x; 1.0213x over previous
#include <cuda_runtime.h>
#include <cuda_fp16.h>
#include <math.h>
#include <cstdint>

// Problem dims (compile-time)
static constexpr int Bsz = 16384;
static constexpr int Dd  = 768;
static constexpr int Kk  = 4;
static constexpr int H1  = 512;
static constexpr int H2  = 256;
static constexpr int KD  = Kk * Dd;        // 3072
static constexpr int NC  = KD + Dd;        // 3840 combined head width

// Scratch (device globals: allocation-free per harness rules)
__device__ float  g_h1[Bsz * H1];
__device__ float  g_h2[Bsz * H2];
__device__ float  g_comb[Bsz * NC];        // [wflat(3072) | logits(768)] per row
__device__ __half g_embh[Bsz * Dd];
__device__ __half g_h1h[Bsz * H1];
__device__ __half g_h2h[Bsz * H2];
__device__ __half g_W1h[Dd * H1];
__device__ __half g_W2h[H1 * H2];
__device__ __half g_Wch[H2 * NC];          // [Wd | Wa] fp16, row stride NC
__device__ float  g_bc[NC];                // [bd | ba]

__device__ __forceinline__ uint32_t smem_u32(const void* p) {
    uint32_t a;
    asm("{ .reg .u64 t; cvta.to.shared.u64 t, %1; cvt.u32.u64 %0, t; }"
        : "=r"(a) : "l"(p));
    return a;
}

__device__ __forceinline__ void cp_async16(uint32_t dst, const void* src) {
    asm volatile("cp.async.cg.shared.global [%0], [%1], 16;"
                 :: "r"(dst), "l"(src) : "memory");
}
#define CP_COMMIT() asm volatile("cp.async.commit_group;" ::: "memory")
#define CP_WAIT(n)  asm volatile("cp.async.wait_group %0;" :: "n"(n) : "memory")

// ===========================================================================
// FP16 mma GEMM: fp16 gmem -> cp.async (3-stage) -> fp16 smem -> ldmatrix
// -> m16n8k16 (fp32 accum).  C[M,N] = A[M,K] @ B[K,N] + bias[N]
// BM=128, BN=128, BK=32. 256 threads = 8 warps in 2x4 (m x n) grid.
// Warp tile 64x32 = 4x4 mma tiles. Requires M%128, N%128, K%32 == 0, K/32 >= 2.
// ===========================================================================
#define BM 128
#define BN 128
#define BKt 32

// Pad strides (halves) for conflict-free ldmatrix row-address phases:
//  A: 40 halves = 80 B/row;  B: 136 halves = 272 B/row
static constexpr int AS_STRIDE = 40;
static constexpr int BS_STRIDE = 136;
static constexpr int AS_ELEMS  = BM * AS_STRIDE;   // 5120 halves
static constexpr int BS_ELEMS  = BKt * BS_STRIDE;  // 4352 halves
static constexpr int NSTAGE    = 3;
static constexpr int GEMM_SMEM_BYTES = NSTAGE * (AS_ELEMS + BS_ELEMS) * 2; // 56832

__global__ __launch_bounds__(256, 2) void mma_gemm(
    const __half* __restrict__ A, const __half* __restrict__ B,
    const float* __restrict__ bias, float* __restrict__ C,
    int M, int N, int Kdim)
{
    extern __shared__ __half hsm[];
    // layout: A stages [0..3), then B stages
    const uint32_t aBase = smem_u32(hsm);
    const uint32_t bBase = aBase + NSTAGE * AS_ELEMS * 2;

    const int tid  = threadIdx.x;
    const int lane = tid & 31;
    const int w    = tid >> 5;
    const int wm   = w >> 2;          // 0..1
    const int wn   = w & 3;           // 0..3
    const int gid  = lane >> 2;       // 0..7
    const int tig  = lane & 3;        // 0..3

    const int m0 = blockIdx.y * BM;
    const int n0 = blockIdx.x * BN;

    float acc[4][4][4];
    #pragma unroll
    for (int i = 0; i < 4; i++)
        #pragma unroll
        for (int j = 0; j < 4; j++)
            #pragma unroll
            for (int r = 0; r < 4; r++) acc[i][j][r] = 0.f;

    const int nch = Kdim / BKt;

    // stage chunk kc into stage buffer s (512 A-segs + 512 B-segs of 16B)
    auto stage = [&](int kc, int s) {
        const uint32_t aB = aBase + s * AS_ELEMS * 2;
        const uint32_t bB = bBase + s * BS_ELEMS * 2;
        const int k0 = kc * BKt;
        #pragma unroll
        for (int it = 0; it < 2; it++) {
            int sid = tid + it * 256;
            int ar = sid >> 2, as = sid & 3;
            cp_async16(aB + (ar * AS_STRIDE + as * 8) * 2,
                       A + (size_t)(m0 + ar) * Kdim + k0 + as * 8);
            int br = sid >> 4, bs = sid & 15;
            cp_async16(bB + (br * BS_STRIDE + bs * 8) * 2,
                       B + (size_t)(k0 + br) * N + n0 + bs * 8);
        }
    };

    // prologue: chunks 0 and 1 (nch >= 2 for all our GEMMs)
    stage(0, 0); CP_COMMIT();
    stage(1, 1); CP_COMMIT();

    for (int kc = 0; kc < nch; kc++) {
        const int cur = kc % NSTAGE;
        if (kc < nch - 1) { CP_WAIT(1); } else { CP_WAIT(0); }
        __syncthreads();   // all warps done reading buffer (kc+2)%3 (iter kc-1)
        if (kc + 2 < nch) { stage(kc + 2, (kc + 2) % NSTAGE); CP_COMMIT(); }

        const uint32_t aCur = aBase + cur * AS_ELEMS * 2;
        const uint32_t bCur = bBase + cur * BS_ELEMS * 2;

        #pragma unroll
        for (int ks = 0; ks < 2; ks++) {
            const int kb = ks * 16;   // k offset in halves
            // A fragments: 4 m-tiles via ldmatrix.x4
            uint32_t af[4][4];
            #pragma unroll
            for (int mi = 0; mi < 4; mi++) {
                const int r = wm * 64 + mi * 16;
                uint32_t addr = aCur
                    + (uint32_t)(r + (lane & 15)) * (AS_STRIDE * 2)
                    + kb * 2 + (lane >> 4) * 16;
                asm volatile(
                    "ldmatrix.sync.aligned.m8n8.x4.shared.b16 {%0,%1,%2,%3}, [%4];"
                    : "=r"(af[mi][0]), "=r"(af[mi][1]),
                      "=r"(af[mi][2]), "=r"(af[mi][3]) : "r"(addr));
            }
            // B fragments: 2 ldmatrix.x4.trans cover 4 n-tiles
            uint32_t bf[4][2];
            #pragma unroll
            for (int nj = 0; nj < 2; nj++) {
                const int c = wn * 32 + nj * 16;
                uint32_t addr = bCur
                    + (uint32_t)(kb + ((lane >> 3) & 1) * 8 + (lane & 7)) * (BS_STRIDE * 2)
                    + (uint32_t)(c + (lane >> 4) * 8) * 2;
                asm volatile(
                    "ldmatrix.sync.aligned.m8n8.x4.trans.shared.b16 {%0,%1,%2,%3}, [%4];"
                    : "=r"(bf[nj * 2][0]), "=r"(bf[nj * 2][1]),
                      "=r"(bf[nj * 2 + 1][0]), "=r"(bf[nj * 2 + 1][1]) : "r"(addr));
            }
            #pragma unroll
            for (int mi = 0; mi < 4; mi++)
                #pragma unroll
                for (int ni = 0; ni < 4; ni++) {
                    asm volatile(
                        "mma.sync.aligned.m16n8k16.row.col.f32.f16.f16.f32 "
                        "{%0,%1,%2,%3}, {%4,%5,%6,%7}, {%8,%9}, {%0,%1,%2,%3};"
                        : "+f"(acc[mi][ni][0]), "+f"(acc[mi][ni][1]),
                          "+f"(acc[mi][ni][2]), "+f"(acc[mi][ni][3])
                        : "r"(af[mi][0]), "r"(af[mi][1]), "r"(af[mi][2]), "r"(af[mi][3]),
                          "r"(bf[ni][0]), "r"(bf[ni][1]));
                }
        }
    }

    // Epilogue: + bias, float2 stores straight from fragments
    #pragma unroll
    for (int mi = 0; mi < 4; mi++) {
        const int r0 = m0 + wm * 64 + mi * 16 + gid;
        #pragma unroll
        for (int ni = 0; ni < 4; ni++) {
            const int c = n0 + wn * 32 + ni * 8 + tig * 2;
            const float2 bv = *(const float2*)(bias + c);
            float2 v0, v1;
            v0.x = acc[mi][ni][0] + bv.x;
            v0.y = acc[mi][ni][1] + bv.y;
            v1.x = acc[mi][ni][2] + bv.x;
            v1.y = acc[mi][ni][3] + bv.y;
            *(float2*)(C + (size_t)r0 * N + c)       = v0;
            *(float2*)(C + (size_t)(r0 + 8) * N + c) = v1;
        }
    }
}

// ===========================================================================
// Converters
// ===========================================================================
__global__ void f32_to_f16_k(const float* __restrict__ s, __half* __restrict__ d,
                             int n)
{
    int i = (blockIdx.x * blockDim.x + threadIdx.x) * 4;
    if (i < n) {
        float4 v = *(const float4*)(s + i);
        __half2* p = (__half2*)(d + i);
        p[0] = __floats2half2_rn(v.x, v.y);
        p[1] = __floats2half2_rn(v.z, v.w);
    }
}

// fp32 [rows, srcCols] -> fp16 at dst[row*dstStride + colOff + col]
__global__ void f32_to_f16_strided(const float* __restrict__ s, __half* __restrict__ d,
                                   int srcCols, int dstStride, int colOff, int n)
{
    int i = (blockIdx.x * blockDim.x + threadIdx.x) * 4;
    if (i < n) {
        int r = i / srcCols, c = i % srcCols;   // srcCols % 4 == 0
        float4 v = *(const float4*)(s + i);
        __half2* p = (__half2*)(d + (size_t)r * dstStride + colOff + c);
        p[0] = __floats2half2_rn(v.x, v.y);
        p[1] = __floats2half2_rn(v.z, v.w);
    }
}

__global__ void bias_concat(const float* __restrict__ bd, const float* __restrict__ ba,
                            float* __restrict__ bc)
{
    int i = blockIdx.x * blockDim.x + threadIdx.x;
    if (i < NC) bc[i] = (i < KD) ? bd[i] : ba[i - KD];
}

// ===========================================================================
// Block reductions
// ===========================================================================
__device__ __forceinline__ float blockSumN(float v, float* red, int nw) {
    #pragma unroll
    for (int o = 16; o > 0; o >>= 1) v += __shfl_down_sync(0xffffffffu, v, o);
    const int lane = threadIdx.x & 31, w = threadIdx.x >> 5;
    if (lane == 0) red[w] = v;
    __syncthreads();
    if (w == 0) {
        v = (lane < nw) ? red[lane] : 0.f;
        #pragma unroll
        for (int o = 4; o > 0; o >>= 1) v += __shfl_down_sync(0xffffffffu, v, o);
        if (lane == 0) red[0] = v;
    }
    __syncthreads();
    float out = red[0];
    __syncthreads();
    return out;
}

__device__ __forceinline__ float blockMaxN(float v, float* red, int nw) {
    #pragma unroll
    for (int o = 16; o > 0; o >>= 1) v = fmaxf(v, __shfl_down_sync(0xffffffffu, v, o));
    const int lane = threadIdx.x & 31, w = threadIdx.x >> 5;
    if (lane == 0) red[w] = v;
    __syncthreads();
    if (w == 0) {
        v = (lane < nw) ? red[lane] : -INFINITY;
        #pragma unroll
        for (int o = 4; o > 0; o >>= 1) v = fmaxf(v, __shfl_down_sync(0xffffffffu, v, o));
        if (lane == 0) red[0] = v;
    }
    __syncthreads();
    float out = red[0];
    __syncthreads();
    return out;
}

// ===========================================================================
// One-pass LayerNorm + ReLU; writes fp32 in place + fp16 shadow for next GEMM
// ===========================================================================
__global__ void ln_relu_v2h(float* __restrict__ x, const float* __restrict__ g,
                            const float* __restrict__ be, __half* __restrict__ xh)
{
    __shared__ float red[8];
    const int H = blockDim.x * 4;
    const int nw = blockDim.x >> 5;
    float4* xp = (float4*)(x + (size_t)blockIdx.x * H);
    __half2* hp = (__half2*)(xh + (size_t)blockIdx.x * H);
    float4 v = xp[threadIdx.x];

    float s  = v.x + v.y + v.z + v.w;
    float s2 = v.x * v.x + v.y * v.y + v.z * v.z + v.w * v.w;
    s  = blockSumN(s, red, nw);
    s2 = blockSumN(s2, red, nw);
    const float mu  = s / H;
    const float var = s2 / H - mu * mu;
    const float rs  = rsqrtf(var + 1e-5f);

    float4 gg = ((const float4*)g)[threadIdx.x];
    float4 bb = ((const float4*)be)[threadIdx.x];
    v.x = fmaxf((v.x - mu) * rs * gg.x + bb.x, 0.f);
    v.y = fmaxf((v.y - mu) * rs * gg.y + bb.y, 0.f);
    v.z = fmaxf((v.z - mu) * rs * gg.z + bb.z, 0.f);
    v.w = fmaxf((v.w - mu) * rs * gg.w + bb.w, 0.f);
    xp[threadIdx.x] = v;
    hp[threadIdx.x * 2]     = __floats2half2_rn(v.x, v.y);
    hp[threadIdx.x * 2 + 1] = __floats2half2_rn(v.z, v.w);
}

// ===========================================================================
// Fused epilogue: softmax -> attn; W = Wflat*attn; Gram-Schmidt K=4; writes
// W_ortho [B,K,D] and attn [B,D]. Reads the combined [wflat|logits] scratch.
// ===========================================================================
__global__ __launch_bounds__(256) void epilogue_kernel(
    const float* __restrict__ comb, float* __restrict__ out)
{
    __shared__ float red[8];
    const int row = blockIdx.x;
    const int tid = threadIdx.x;
    constexpr int J = Dd / 256;  // 3
    const float* crow = comb + (size_t)row * NC;

    float l[J];
    float m = -INFINITY;
    #pragma unroll
    for (int j = 0; j < J; j++) {
        l[j] = crow[KD + tid + j * 256];
        m = fmaxf(m, l[j]);
    }
    m = blockMaxN(m, red, 8);
    float e[J], s = 0.f;
    #pragma unroll
    for (int j = 0; j < J; j++) { e[j] = expf(l[j] - m); s += e[j]; }
    s = blockSumN(s, red, 8);
    const float inv_s = 1.f / s;
    float attn[J];
    float* out_attn = out + (size_t)Bsz * KD;
    #pragma unroll
    for (int j = 0; j < J; j++) {
        attn[j] = e[j] * inv_s;
        out_attn[(size_t)row * Dd + tid + j * 256] = attn[j];
    }

    float wv[Kk][J];
    #pragma unroll
    for (int k = 0; k < Kk; k++)
        #pragma unroll
        for (int j = 0; j < J; j++)
            wv[k][j] = crow[k * Dd + tid + j * 256] * attn[j];

    #pragma unroll
    for (int k = 0; k < Kk; k++) {
        #pragma unroll
        for (int p = 0; p < k; p++) {
            float d = 0.f;
            #pragma unroll
            for (int j = 0; j < J; j++) d += wv[k][j] * wv[p][j];
            d = blockSumN(d, red, 8);
            #pragma unroll
            for (int j = 0; j < J; j++) wv[k][j] -= d * wv[p][j];
        }
        float n2 = 0.f;
        #pragma unroll
        for (int j = 0; j < J; j++) n2 += wv[k][j] * wv[k][j];
        n2 = blockSumN(n2, red, 8);
        const float inv = 1.f / fmaxf(sqrtf(n2), 1e-12f);
        #pragma unroll
        for (int j = 0; j < J; j++) {
            wv[k][j] *= inv;
            out[(size_t)row * KD + k * Dd + tid + j * 256] = wv[k][j];
        }
    }
}

// ===========================================================================
extern "C" void kernel_launch(void* const* d_in, const int* in_sizes, int n_in,
                              void* d_out, int out_size)
{
    const float* emb = (const float*)d_in[0];
    const float* W1  = (const float*)d_in[1];
    const float* b1  = (const float*)d_in[2];
    const float* g1  = (const float*)d_in[3];
    const float* be1 = (const float*)d_in[4];
    const float* W2  = (const float*)d_in[5];
    const float* b2  = (const float*)d_in[6];
    const float* g2  = (const float*)d_in[7];
    const float* be2 = (const float*)d_in[8];
    const float* Wd  = (const float*)d_in[9];
    const float* bd  = (const float*)d_in[10];
    const float* Wa  = (const float*)d_in[11];
    const float* ba  = (const float*)d_in[12];
    float* out = (float*)d_out;

    float *h1, *h2, *comb, *bc;
    __half *embh, *h1h, *h2h, *W1h, *W2h, *Wch;
    cudaGetSymbolAddress((void**)&h1, g_h1);
    cudaGetSymbolAddress((void**)&h2, g_h2);
    cudaGetSymbolAddress((void**)&comb, g_comb);
    cudaGetSymbolAddress((void**)&bc, g_bc);
    cudaGetSymbolAddress((void**)&embh, g_embh);
    cudaGetSymbolAddress((void**)&h1h, g_h1h);
    cudaGetSymbolAddress((void**)&h2h, g_h2h);
    cudaGetSymbolAddress((void**)&W1h, g_W1h);
    cudaGetSymbolAddress((void**)&W2h, g_W2h);
    cudaGetSymbolAddress((void**)&Wch, g_Wch);

    cudaFuncSetAttribute(mma_gemm, cudaFuncAttributeMaxDynamicSharedMemorySize,
                         GEMM_SMEM_BYTES);

    auto cvt = [&](const float* s, __half* d, int n) {
        f32_to_f16_k<<<(n / 4 + 255) / 256, 256>>>(s, d, n);
    };
    cvt(emb, embh, Bsz * Dd);
    cvt(W1, W1h, Dd * H1);
    cvt(W2, W2h, H1 * H2);
    // combined head weights [Wd | Wa] (row stride NC) + combined bias
    f32_to_f16_strided<<<(H2 * KD / 4 + 255) / 256, 256>>>(Wd, Wch, KD, NC, 0,  H2 * KD);
    f32_to_f16_strided<<<(H2 * Dd / 4 + 255) / 256, 256>>>(Wa, Wch, Dd, NC, KD, H2 * Dd);
    bias_concat<<<(NC + 255) / 256, 256>>>(bd, ba, bc);

    // Layer 1
    mma_gemm<<<dim3(H1 / BN, Bsz / BM), 256, GEMM_SMEM_BYTES>>>(embh, W1h, b1, h1, Bsz, H1, Dd);
    ln_relu_v2h<<<Bsz, H1 / 4>>>(h1, g1, be1, h1h);
    // Layer 2
    mma_gemm<<<dim3(H2 / BN, Bsz / BM), 256, GEMM_SMEM_BYTES>>>(h1h, W2h, b2, h2, Bsz, H2, H1);
    ln_relu_v2h<<<Bsz, H2 / 4>>>(h2, g2, be2, h2h);
    // Combined heads: comb = h2 @ [Wd|Wa] + [bd|ba]
    mma_gemm<<<dim3(NC / BN, Bsz / BM), 256, GEMM_SMEM_BYTES>>>(h2h, Wch, bc, comb, Bsz, NC, H2);
    // softmax + modulate + Gram-Schmidt
    epilogue_kernel<<<Bsz, 256>>>(comb, out);
}